// round 5
// baseline (speedup 1.0000x reference)
#include <cuda_runtime.h>
#include <math.h>
#include <stdint.h>

// dims
#define Bn   32
#define Sn   512
#define In   256
#define Hn   512
#define G4n  2048
#define En   1024
#define NBLK 128
#define NPACK 2176   // 1024 K-rows + 1024 V-rows + 64 Q15-rows + 64 zero pad

// ---------------- static device scratch ----------------
__device__ float d_xg [(size_t)Sn * G4n * Bn];   // fwd input gates [s][g][b]  (128 MB)
__device__ float d_xgb[(size_t)16 * G4n * Bn];   // bwd input gates [srel][g][b]
__device__ float d_h[2][Hn * Bn];                // double-buffered h state [k][b]
__device__ float d_hsel[(size_t)Bn * 16 * En];   // h at s in [496,512): [(b*16+srel)][e]
__device__ float d_wpack[(size_t)NPACK * En];
__device__ float d_bpack[NPACK];
__device__ float d_att[(size_t)512 * NPACK];     // per (b,srel): K(1024) V(1024) Q15(64)
__device__ float d_weff[En];
__device__ float d_scal0;
__device__ unsigned d_barcnt;
__device__ volatile unsigned d_bargen;

__device__ __forceinline__ float sigf(float x) { return 1.0f / (1.0f + expf(-x)); }

__device__ __forceinline__ void gridbar() {
    __syncthreads();
    if (threadIdx.x == 0) {
        __threadfence();
        unsigned gen = d_bargen;
        if (atomicAdd(&d_barcnt, 1u) == NBLK - 1u) {
            d_barcnt = 0u;
            __threadfence();
            d_bargen = gen + 1u;
        } else {
            while (d_bargen == gen) {}
            __threadfence();
        }
    }
    __syncthreads();
}

// ======================= K1: xg = x @ W_ih^T + b ===========================
// M = 16384 fwd rows (m = s*32+b) + 512 bwd rows (s in [496,512)).
// 128x128 tile, 256 thr, 8x8 microtile, BK=8. Output TRANSPOSED: [s][g][b].
__global__ void __launch_bounds__(256) k_xg(
    const float* __restrict__ x,
    const float* __restrict__ Wihf, const float* __restrict__ bf,
    const float* __restrict__ Wihb, const float* __restrict__ bb)
{
    __shared__ float A_sm[8][128];
    __shared__ float B_sm[8][128];
    const int tid = threadIdx.x;
    const bool bwd = (blockIdx.y >= 128);
    const float* __restrict__ W    = bwd ? Wihb : Wihf;
    const float* __restrict__ bias = bwd ? bb   : bf;
    const int m0 = blockIdx.y * 128;
    const int n0 = blockIdx.x * 128;

    const int lrow = tid >> 1;
    const int lk   = (tid & 1) * 4;
    const int mg = m0 + lrow;
    int sA, bA;
    if (!bwd) { sA = mg >> 5; bA = mg & 31; }
    else { const int ml = mg - 16384; sA = 496 + (ml >> 5); bA = ml & 31; }
    const float* __restrict__ xrow = x + ((size_t)bA * Sn + sA) * In;
    const float* __restrict__ wrow = W + (size_t)(n0 + lrow) * In;

    const int tm = tid >> 4;
    const int tn = tid & 15;

    float acc[8][8];
#pragma unroll
    for (int i = 0; i < 8; ++i)
#pragma unroll
        for (int j = 0; j < 8; ++j) acc[i][j] = 0.0f;

    for (int k0 = 0; k0 < In; k0 += 8) {
        float4 av = *(const float4*)(xrow + k0 + lk);
        float4 bv = *(const float4*)(wrow + k0 + lk);
        __syncthreads();
        A_sm[lk + 0][lrow] = av.x; A_sm[lk + 1][lrow] = av.y;
        A_sm[lk + 2][lrow] = av.z; A_sm[lk + 3][lrow] = av.w;
        B_sm[lk + 0][lrow] = bv.x; B_sm[lk + 1][lrow] = bv.y;
        B_sm[lk + 2][lrow] = bv.z; B_sm[lk + 3][lrow] = bv.w;
        __syncthreads();
#pragma unroll
        for (int kk = 0; kk < 8; ++kk) {
            float a[8], b[8];
            *(float4*)(a + 0) = *(const float4*)&A_sm[kk][tm * 8 + 0];
            *(float4*)(a + 4) = *(const float4*)&A_sm[kk][tm * 8 + 4];
            *(float4*)(b + 0) = *(const float4*)&B_sm[kk][tn * 8 + 0];
            *(float4*)(b + 4) = *(const float4*)&B_sm[kk][tn * 8 + 4];
#pragma unroll
            for (int i = 0; i < 8; ++i)
#pragma unroll
                for (int j = 0; j < 8; ++j) acc[i][j] += a[i] * b[j];
        }
    }

    float bvals[8];
#pragma unroll
    for (int j = 0; j < 8; ++j) bvals[j] = bias[n0 + tn * 8 + j];
#pragma unroll
    for (int i = 0; i < 8; ++i) {
        const int m = m0 + tm * 8 + i;
        if (!bwd) {
            const int s = m >> 5, b = m & 31;
            float* base = d_xg + ((size_t)s * G4n) * Bn + b;
#pragma unroll
            for (int j = 0; j < 8; ++j)
                base[(size_t)(n0 + tn * 8 + j) * Bn] = acc[i][j] + bvals[j];
        } else {
            const int ml = m - 16384;
            const int srel = ml >> 5, b = ml & 31;
            float* base = d_xgb + ((size_t)srel * G4n) * Bn + b;
#pragma unroll
            for (int j = 0; j < 8; ++j)
                base[(size_t)(n0 + tn * 8 + j) * Bn] = acc[i][j] + bvals[j];
        }
    }
}

// ======================= K2: persistent LSTM recurrence ====================
// 128 blocks; block owns 4 h-cells (hbase=bid*4), all 32 batches.
// W rows (16 = 4 gate types x 4 cells) preloaded in smem for all steps.
// One grid barrier per step; h state double-buffered in [k][b] layout.
__global__ void __launch_bounds__(256) k_rec(
    const float* __restrict__ Whh, int steps, int dircol)
{
    extern __shared__ float smem[];
    float* h_sm = smem;                       // [512][32]
    float* W_sm = smem + Hn * Bn;             // [512][16]
    float* part = W_sm + Hn * 16;             // [2][16][32]

    const int tid = threadIdx.x;
    const int hbase = blockIdx.x * 4;

    // preload W: W_sm[k][r], r = q*4+j -> Whh row q*512 + hbase + j
    {
        const int r = tid & 15, kseg = tid >> 4;   // kseg 0..15 covers 32 k each
        const int q = r >> 2, j = r & 3;
        const float* wr = Whh + (size_t)(q * Hn + hbase + j) * Hn + kseg * 32;
#pragma unroll
        for (int kk = 0; kk < 32; kk += 4) {
            float4 w4 = *(const float4*)(wr + kk);
            const int kb = kseg * 32 + kk;
            W_sm[(kb + 0) * 16 + r] = w4.x;
            W_sm[(kb + 1) * 16 + r] = w4.y;
            W_sm[(kb + 2) * 16 + r] = w4.z;
            W_sm[(kb + 3) * 16 + r] = w4.w;
        }
    }

    const int ks = tid >> 7;            // K half
    const int rr = (tid >> 4) & 7;      // row pair
    const int bb = tid & 15;            // batch pair
    float c_reg = 0.0f;

    for (int t = 0; t < steps; ++t) {
        // stage h(t-1)
        if (t == 0) {
            const float4 z4 = make_float4(0.f, 0.f, 0.f, 0.f);
            for (int i = tid; i < Hn * Bn / 4; i += 256) ((float4*)h_sm)[i] = z4;
        } else {
            const float4* src = (const float4*)d_h[(t - 1) & 1];
            for (int i = tid; i < Hn * Bn / 4; i += 256)
                ((float4*)h_sm)[i] = __ldcg(src + i);
        }
        __syncthreads();

        // GEMM: 16 rows x 32 b, K split in 2 halves of 256
        float a00 = 0.f, a01 = 0.f, a10 = 0.f, a11 = 0.f;
        const float* hp = h_sm + (ks * 256) * Bn + bb * 2;
        const float* wp = W_sm + (ks * 256) * 16 + rr * 2;
#pragma unroll 8
        for (int k = 0; k < 256; ++k) {
            float2 h2 = *(const float2*)hp; hp += Bn;
            float2 w2 = *(const float2*)wp; wp += 16;
            a00 += w2.x * h2.x; a01 += w2.x * h2.y;
            a10 += w2.y * h2.x; a11 += w2.y * h2.y;
        }
        part[ks * 512 + (rr * 2 + 0) * 32 + bb * 2 + 0] = a00;
        part[ks * 512 + (rr * 2 + 0) * 32 + bb * 2 + 1] = a01;
        part[ks * 512 + (rr * 2 + 1) * 32 + bb * 2 + 0] = a10;
        part[ks * 512 + (rr * 2 + 1) * 32 + bb * 2 + 1] = a11;
        __syncthreads();

        // gates + state update: 128 cells (4 j x 32 b)
        if (tid < 128) {
            const int b = tid & 31, j = tid >> 5;
            const int xs = dircol ? (steps - 1 - t) : t;
            const float* xb = (dircol ? d_xgb : d_xg)
                            + ((size_t)xs * G4n + hbase + j) * Bn + b;
            float gi = part[(0 + j) * 32 + b]  + part[512 + (0 + j) * 32 + b]  + xb[0];
            float gf = part[(4 + j) * 32 + b]  + part[512 + (4 + j) * 32 + b]  + xb[(size_t)512 * Bn];
            float gg = part[(8 + j) * 32 + b]  + part[512 + (8 + j) * 32 + b]  + xb[(size_t)1024 * Bn];
            float go = part[(12 + j) * 32 + b] + part[512 + (12 + j) * 32 + b] + xb[(size_t)1536 * Bn];
            c_reg = sigf(gf) * c_reg + sigf(gi) * tanhf(gg);
            const float hv = sigf(go) * tanhf(c_reg);
            __stcg(&d_h[t & 1][(hbase + j) * Bn + b], hv);
            const int srel = dircol ? xs : (t - 496);
            if (srel >= 0)
                d_hsel[((size_t)b * 16 + srel) * En + dircol * Hn + hbase + j] = hv;
        }
        gridbar();
    }
}

// ======================= K3: weight packing + folds ========================
__global__ void __launch_bounds__(256) k_pack(
    const float* __restrict__ Wk, const float* __restrict__ bk,
    const float* __restrict__ Wv, const float* __restrict__ bv,
    const float* __restrict__ Wq, const float* __restrict__ bq)
{
    const int r = blockIdx.x;
    const float* src = nullptr;
    float bsv = 0.0f;
    if (r < 1024)      { src = Wk + (size_t)r * En;                bsv = bk[r]; }
    else if (r < 2048) { src = Wv + (size_t)(r - 1024) * En;       bsv = bv[r - 1024]; }
    else if (r < 2112) { src = Wq + (size_t)(960 + r - 2048) * En; bsv = bq[960 + r - 2048]; }
    float* dst = d_wpack + (size_t)r * En;
    if (src) {
        for (int i = threadIdx.x * 4; i < En; i += 1024)
            *(float4*)(dst + i) = *(const float4*)(src + i);
    } else {
        const float4 z4 = make_float4(0.f, 0.f, 0.f, 0.f);
        for (int i = threadIdx.x * 4; i < En; i += 1024) *(float4*)(dst + i) = z4;
    }
    if (threadIdx.x == 0) d_bpack[r] = bsv;
}

__global__ void __launch_bounds__(256) k_weff(
    const float* __restrict__ Wfc, const float* __restrict__ Wo,
    const float* __restrict__ bo,  const float* __restrict__ bfc)
{
    const int i = blockIdx.x * 256 + threadIdx.x;   // 0..1023
    float acc = 0.0f;
    for (int e = 0; e < En; ++e) acc += Wfc[e] * Wo[(size_t)e * En + i];
    d_weff[i] = acc;
    if (blockIdx.x == 0) {
        __shared__ float red[256];
        float p = 0.0f;
        for (int e = threadIdx.x; e < En; e += 256) p += Wfc[e] * bo[e];
        red[threadIdx.x] = p; __syncthreads();
        for (int o = 128; o > 0; o >>= 1) {
            if (threadIdx.x < o) red[threadIdx.x] += red[threadIdx.x + o];
            __syncthreads();
        }
        if (threadIdx.x == 0) d_scal0 = red[0] + bfc[0];
    }
}

// ======================= K4: QKV GEMM ======================================
// d_att[m][n] = d_hsel[m] . d_wpack[n] + d_bpack[n]; M=512, N=2176, K=1024.
__global__ void __launch_bounds__(256) k_qkv()
{
    __shared__ float A_sm[8][128];
    __shared__ float B_sm[8][128];
    const int tid = threadIdx.x;
    const int m0 = blockIdx.y * 128;
    const int n0 = blockIdx.x * 128;
    const int lrow = tid >> 1;
    const int lk   = (tid & 1) * 4;
    const float* __restrict__ arow = d_hsel + (size_t)(m0 + lrow) * En;
    const float* __restrict__ wrow = d_wpack + (size_t)(n0 + lrow) * En;
    const int tm = tid >> 4;
    const int tn = tid & 15;

    float acc[8][8];
#pragma unroll
    for (int i = 0; i < 8; ++i)
#pragma unroll
        for (int j = 0; j < 8; ++j) acc[i][j] = 0.0f;

    for (int k0 = 0; k0 < En; k0 += 8) {
        float4 av = *(const float4*)(arow + k0 + lk);
        float4 bv = *(const float4*)(wrow + k0 + lk);
        __syncthreads();
        A_sm[lk + 0][lrow] = av.x; A_sm[lk + 1][lrow] = av.y;
        A_sm[lk + 2][lrow] = av.z; A_sm[lk + 3][lrow] = av.w;
        B_sm[lk + 0][lrow] = bv.x; B_sm[lk + 1][lrow] = bv.y;
        B_sm[lk + 2][lrow] = bv.z; B_sm[lk + 3][lrow] = bv.w;
        __syncthreads();
#pragma unroll
        for (int kk = 0; kk < 8; ++kk) {
            float a[8], b[8];
            *(float4*)(a + 0) = *(const float4*)&A_sm[kk][tm * 8 + 0];
            *(float4*)(a + 4) = *(const float4*)&A_sm[kk][tm * 8 + 4];
            *(float4*)(b + 0) = *(const float4*)&B_sm[kk][tn * 8 + 0];
            *(float4*)(b + 4) = *(const float4*)&B_sm[kk][tn * 8 + 4];
#pragma unroll
            for (int i = 0; i < 8; ++i)
#pragma unroll
                for (int j = 0; j < 8; ++j) acc[i][j] += a[i] * b[j];
        }
    }

    float bvals[8];
#pragma unroll
    for (int j = 0; j < 8; ++j) bvals[j] = d_bpack[n0 + tn * 8 + j];
#pragma unroll
    for (int i = 0; i < 8; ++i) {
        const int m = m0 + tm * 8 + i;
        float* orow = d_att + (size_t)m * NPACK + n0 + tn * 8;
        float4 o0 = make_float4(acc[i][0] + bvals[0], acc[i][1] + bvals[1],
                                acc[i][2] + bvals[2], acc[i][3] + bvals[3]);
        float4 o1 = make_float4(acc[i][4] + bvals[4], acc[i][5] + bvals[5],
                                acc[i][6] + bvals[6], acc[i][7] + bvals[7]);
        *(float4*)(orow + 0) = o0;
        *(float4*)(orow + 4) = o1;
    }
}

// ======================= K5: head-gram softmax + fold ======================
// Per (b, srel): scores[kh] = 0.125 * Q15 . K[kh]; softmax over kh;
// pre[d] = sum_kh attn[kh] * V[kh][d]; out accumulates w_eff[srel*64+d]*pre[d].
__global__ void __launch_bounds__(512) k_attn(float* __restrict__ out)
{
    __shared__ float sm[16];
    const int b = blockIdx.x;
    const int w = threadIdx.x >> 5;     // srel
    const int lane = threadIdx.x & 31;
    const float* __restrict__ row = d_att + (size_t)(b * 16 + w) * NPACK;

    float sc = 0.0f;
    if (lane < 16) {
        const float4* q4 = (const float4*)(row + 2048);
        const float4* k4 = (const float4*)(row + lane * 64);
#pragma unroll
        for (int i = 0; i < 16; ++i) {
            float4 q = q4[i], k = k4[i];
            sc += q.x * k.x + q.y * k.y + q.z * k.z + q.w * k.w;
        }
        sc *= 0.125f;
    } else sc = -INFINITY;

    float m = sc;
#pragma unroll
    for (int o = 8; o > 0; o >>= 1) m = fmaxf(m, __shfl_xor_sync(0xffffffffu, m, o));
    float e = (lane < 16) ? expf(sc - m) : 0.0f;
    float den = e;
#pragma unroll
    for (int o = 8; o > 0; o >>= 1) den += __shfl_xor_sync(0xffffffffu, den, o);

    float pre0 = 0.0f, pre1 = 0.0f;
#pragma unroll
    for (int kh = 0; kh < 16; ++kh) {
        const float a = __shfl_sync(0xffffffffu, e, kh);
        pre0 += a * row[1024 + kh * 64 + lane];
        pre1 += a * row[1024 + kh * 64 + lane + 32];
    }
    const float dn = __shfl_sync(0xffffffffu, den, 0);
    float acc = (pre0 * d_weff[w * 64 + lane] + pre1 * d_weff[w * 64 + lane + 32]) / dn;
#pragma unroll
    for (int o = 16; o > 0; o >>= 1) acc += __shfl_xor_sync(0xffffffffu, acc, o);
    if (lane == 0) sm[w] = acc;
    __syncthreads();
    if (threadIdx.x == 0) {
        float z = d_scal0;
#pragma unroll
        for (int h = 0; h < 16; ++h) z += sm[h];
        out[b] = 1.0f / (1.0f + expf(-z));
    }
}

// ======================= launch ===========================================
extern "C" void kernel_launch(void* const* d_in, const int* in_sizes, int n_in,
                              void* d_out, int out_size)
{
    const float* x    = (const float*)d_in[0];
    const float* Wihf = (const float*)d_in[1];
    const float* Whhf = (const float*)d_in[2];
    const float* bf   = (const float*)d_in[3];
    const float* Wihb = (const float*)d_in[4];
    const float* Whhb = (const float*)d_in[5];
    const float* bb   = (const float*)d_in[6];
    const float* Wq   = (const float*)d_in[7];
    const float* bq   = (const float*)d_in[8];
    const float* Wk   = (const float*)d_in[9];
    const float* bk   = (const float*)d_in[10];
    const float* Wv   = (const float*)d_in[11];
    const float* bv   = (const float*)d_in[12];
    const float* Wo   = (const float*)d_in[13];
    const float* bo   = (const float*)d_in[14];
    const float* Wfc  = (const float*)d_in[15];
    const float* bfc  = (const float*)d_in[16];
    float* out = (float*)d_out;

    const int rec_smem = (Hn * Bn + Hn * 16 + 2 * 16 * 32) * sizeof(float); // 100 KB
    cudaFuncSetAttribute(k_rec, cudaFuncAttributeMaxDynamicSharedMemorySize, rec_smem);

    k_xg<<<dim3(16, 132), 256>>>(x, Wihf, bf, Wihb, bb);
    k_rec<<<NBLK, 256, rec_smem>>>(Whhf, 512, 0);
    k_rec<<<NBLK, 256, rec_smem>>>(Whhb, 16, 1);
    k_pack<<<NPACK, 256>>>(Wk, bk, Wv, bv, Wq, bq);
    k_weff<<<4, 256>>>(Wfc, Wo, bo, bfc);
    k_qkv<<<dim3(17, 4), 256>>>();
    k_attn<<<32, 512>>>(out);
}

// round 7
// speedup vs baseline: 1.2167x; 1.2167x over previous
#include <cuda_runtime.h>
#include <math.h>
#include <stdint.h>

// dims
#define Bn   32
#define Sn   512
#define In   256
#define Hn   512
#define G4n  2048
#define En   1024
#define NPACK 2176   // 1024 K-rows + 1024 V-rows + 64 Q15-rows + 64 zero pad
#define NGRP 4       // batch groups (8 batches each), 32 blocks per group

// ---------------- static device scratch ----------------
__device__ float d_xg [(size_t)Sn * Bn * G4n];   // fwd input gates, row m=s*32+b, col g (128 MB)
__device__ float d_xgb[(size_t)16 * Bn * G4n];   // bwd input gates, row m=srel*32+b
__device__ unsigned long long d_hdup[2][NGRP][Hn][8]; // h state, duplicated f32x2, dbl-buffered
__device__ float d_hsel[(size_t)Bn * 16 * En];   // h at s in [496,512): [(b*16+srel)][e]
__device__ float d_wpack[(size_t)NPACK * En];
__device__ float d_bpack[NPACK];
__device__ float d_att[(size_t)512 * NPACK];     // per (b,srel): K(1024) V(1024) Q15(64)
__device__ float d_weff[En];
__device__ float d_scal0;
__device__ unsigned d_gcnt[NGRP];
__device__ volatile unsigned d_ggen[NGRP];

__device__ __forceinline__ float sigf(float x) { return 1.0f / (1.0f + expf(-x)); }

// ---- packed fp32x2 helpers (bit-exact 2x fp32 FMA; sm_100+ PTX) ----
__device__ __forceinline__ unsigned long long ffma2(
    unsigned long long a, unsigned long long b, unsigned long long c) {
    unsigned long long d;
    asm("fma.rn.f32x2 %0, %1, %2, %3;" : "=l"(d) : "l"(a), "l"(b), "l"(c));
    return d;
}
__device__ __forceinline__ unsigned long long pk2(float x, float y) {
    unsigned long long r;
    asm("mov.b64 %0, {%1, %2};" : "=l"(r)
        : "r"(__float_as_uint(x)), "r"(__float_as_uint(y)));
    return r;
}
__device__ __forceinline__ void upk2(unsigned long long v, float& x, float& y) {
    unsigned lo, hi;
    asm("mov.b64 {%0, %1}, %2;" : "=r"(lo), "=r"(hi) : "l"(v));
    x = __uint_as_float(lo); y = __uint_as_float(hi);
}

// ---- per-group software barrier (32 co-resident blocks per group) ----
__device__ __forceinline__ void gridbar(int g) {
    __syncthreads();
    if (threadIdx.x == 0) {
        __threadfence();
        unsigned gen = d_ggen[g];
        if (atomicAdd(&d_gcnt[g], 1u) == 31u) {
            d_gcnt[g] = 0u;
            __threadfence();
            d_ggen[g] = gen + 1u;
        } else {
            while (d_ggen[g] == gen) { }
        }
        __threadfence();
    }
    __syncthreads();
}

// ======================= K1: xg = x @ W_ih^T + b ===========================
// M = 16384 fwd rows (m=s*32+b) + 512 bwd rows (s in [496,512)).
// 128x128 tile, 256 thr, 8x8 microtile via f32x2, BK=8. Row-major output.
__global__ void __launch_bounds__(256) k_xg(
    const float* __restrict__ x,
    const float* __restrict__ Wihf, const float* __restrict__ bf,
    const float* __restrict__ Wihb, const float* __restrict__ bb)
{
    __shared__ __align__(16) float A_sm[8][128];
    __shared__ __align__(16) float B_sm[8][128];
    const int tid = threadIdx.x;
    const bool bwd = (blockIdx.y >= 128);
    const float* __restrict__ W    = bwd ? Wihb : Wihf;
    const float* __restrict__ bias = bwd ? bb   : bf;
    const int m0 = blockIdx.y * 128;
    const int n0 = blockIdx.x * 128;

    const int lrow = tid >> 1;
    const int lk   = (tid & 1) * 4;
    const int mg = m0 + lrow;
    int sA, bA;
    if (!bwd) { sA = mg >> 5; bA = mg & 31; }
    else { const int ml = mg - 16384; sA = 496 + (ml >> 5); bA = ml & 31; }
    const float* __restrict__ xrow = x + ((size_t)bA * Sn + sA) * In;
    const float* __restrict__ wrow = W + (size_t)(n0 + lrow) * In;

    const int tm = tid >> 4;
    const int tn = tid & 15;

    unsigned long long acc[8][4];
#pragma unroll
    for (int i = 0; i < 8; ++i)
#pragma unroll
        for (int p = 0; p < 4; ++p) acc[i][p] = 0ull;

    for (int k0 = 0; k0 < In; k0 += 8) {
        float4 av = *(const float4*)(xrow + k0 + lk);
        float4 bv = *(const float4*)(wrow + k0 + lk);
        __syncthreads();
        A_sm[lk + 0][lrow] = av.x; A_sm[lk + 1][lrow] = av.y;
        A_sm[lk + 2][lrow] = av.z; A_sm[lk + 3][lrow] = av.w;
        B_sm[lk + 0][lrow] = bv.x; B_sm[lk + 1][lrow] = bv.y;
        B_sm[lk + 2][lrow] = bv.z; B_sm[lk + 3][lrow] = bv.w;
        __syncthreads();
#pragma unroll
        for (int kk = 0; kk < 8; ++kk) {
            float a[8];
            *(float4*)(a + 0) = *(const float4*)&A_sm[kk][tm * 8 + 0];
            *(float4*)(a + 4) = *(const float4*)&A_sm[kk][tm * 8 + 4];
            ulonglong2 b01 = *(const ulonglong2*)&B_sm[kk][tn * 8 + 0];
            ulonglong2 b23 = *(const ulonglong2*)&B_sm[kk][tn * 8 + 4];
            unsigned long long bb4[4] = {b01.x, b01.y, b23.x, b23.y};
#pragma unroll
            for (int i = 0; i < 8; ++i) {
                const unsigned long long ad = pk2(a[i], a[i]);
#pragma unroll
                for (int p = 0; p < 4; ++p) acc[i][p] = ffma2(ad, bb4[p], acc[i][p]);
            }
        }
    }

    float bvals[8];
#pragma unroll
    for (int j = 0; j < 8; ++j) bvals[j] = bias[n0 + tn * 8 + j];
#pragma unroll
    for (int i = 0; i < 8; ++i) {
        float c[8];
#pragma unroll
        for (int p = 0; p < 4; ++p) upk2(acc[i][p], c[2 * p], c[2 * p + 1]);
        const int m = m0 + tm * 8 + i;
        float* orow = (!bwd ? d_xg + (size_t)m * G4n
                            : d_xgb + (size_t)(m - 16384) * G4n) + n0 + tn * 8;
        float4 o0 = make_float4(c[0] + bvals[0], c[1] + bvals[1],
                                c[2] + bvals[2], c[3] + bvals[3]);
        float4 o1 = make_float4(c[4] + bvals[4], c[5] + bvals[5],
                                c[6] + bvals[6], c[7] + bvals[7]);
        *(float4*)(orow + 0) = o0;
        *(float4*)(orow + 4) = o1;
    }
}

// ======================= K2: persistent LSTM recurrence ====================
// 128 blocks = 4 independent batch-groups x 32 blocks.
// Block (g, rblk): owns 16 h-cells (cbase=rblk*16), all 4 gate types,
// 8 batches of group g. W_hh slice (64 rows x 512) in smem for all steps.
// h state stored globally PRE-DUPLICATED as f32x2 pairs -> inner loop is
// 3x LDS.128 + 8x FFMA2 per k. One group-barrier per step.
__global__ void __launch_bounds__(256) k_rec(
    const float* __restrict__ Whh, int steps, int dircol)
{
    extern __shared__ float smem[];
    float* W_sm = smem;                                        // [512][64]
    unsigned long long* hdup = (unsigned long long*)(smem + 512 * 64); // [512][8]
    float* part = (float*)(hdup + 512 * 8);                    // [8][8][64]

    const int tid  = threadIdx.x;
    const int g    = blockIdx.x & 3;
    const int rblk = blockIdx.x >> 2;
    const int cbase = rblk * 16;

    // preload W transposed: W_sm[k][r], r = q*16+j  <- Whh row q*512+cbase+j
    {
        const int r = tid & 63;
        const int q = r >> 4, j = r & 15;
        const int kblk = tid >> 6;            // 4 chunks of 128 k
        const float* wr = Whh + (size_t)(q * Hn + cbase + j) * Hn + kblk * 128;
#pragma unroll 4
        for (int kk = 0; kk < 128; kk += 4) {
            float4 w4 = *(const float4*)(wr + kk);
            const int kb = kblk * 128 + kk;
            W_sm[(kb + 0) * 64 + r] = w4.x;
            W_sm[(kb + 1) * 64 + r] = w4.y;
            W_sm[(kb + 2) * 64 + r] = w4.z;
            W_sm[(kb + 3) * 64 + r] = w4.w;
        }
    }

    const int ks = tid >> 5;            // K-split 8 (warp-uniform)
    const int tg = (tid >> 1) & 15;     // row-quad
    const int tb = tid & 1;             // batch-quad (2 x 4 batches)

    // PhaseB identity (threads 0..127): cell pb_j of batch pb_b
    const int pb_b = tid >> 4;
    const int pb_j = tid & 15;
    const int bglob = g * 8 + pb_b;

    float c_reg = 0.0f;

    for (int t = 0; t < steps; ++t) {
        const int xs = dircol ? (steps - 1 - t) : t;

        // prefetch this step's input-gate values (independent of recurrence)
        float xgi = 0.f, xgf = 0.f, xgg = 0.f, xgo = 0.f;
        if (tid < 128) {
            const float* xb = (dircol ? d_xgb : d_xg)
                            + (size_t)(xs * 32 + bglob) * G4n + cbase + pb_j;
            xgi = __ldg(xb);
            xgf = __ldg(xb + 512);
            xgg = __ldg(xb + 1024);
            xgo = __ldg(xb + 1536);
        }

        // stage h(t-1) duplicated pairs into smem (32 KB)
        if (t == 0) {
            for (int i = tid; i < 4096; i += 256) hdup[i] = 0ull;
        } else {
            const uint4* src = (const uint4*)&d_hdup[(t - 1) & 1][g][0][0];
            uint4* dst = (uint4*)hdup;
#pragma unroll
            for (int i = 0; i < 8; ++i)
                dst[tid + 256 * i] = __ldcg(src + tid + 256 * i);
        }
        __syncthreads();

        // GEMM: 64 rows x 8 batches, K-slice [ks*64, ks*64+64)
        unsigned long long acc[2][4];
#pragma unroll
        for (int p = 0; p < 2; ++p)
#pragma unroll
            for (int j = 0; j < 4; ++j) acc[p][j] = 0ull;

        const float* wp = W_sm + (ks * 64) * 64 + tg * 4;
        const unsigned long long* hp = hdup + (ks * 64) * 8 + tb * 4;
#pragma unroll 4
        for (int k = 0; k < 64; ++k) {
            ulonglong2 w2  = *(const ulonglong2*)wp;       wp += 64;
            ulonglong2 h01 = *(const ulonglong2*)hp;
            ulonglong2 h23 = *(const ulonglong2*)(hp + 2); hp += 8;
            acc[0][0] = ffma2(w2.x, h01.x, acc[0][0]);
            acc[1][0] = ffma2(w2.y, h01.x, acc[1][0]);
            acc[0][1] = ffma2(w2.x, h01.y, acc[0][1]);
            acc[1][1] = ffma2(w2.y, h01.y, acc[1][1]);
            acc[0][2] = ffma2(w2.x, h23.x, acc[0][2]);
            acc[1][2] = ffma2(w2.y, h23.x, acc[1][2]);
            acc[0][3] = ffma2(w2.x, h23.y, acc[0][3]);
            acc[1][3] = ffma2(w2.y, h23.y, acc[1][3]);
        }
#pragma unroll
        for (int j = 0; j < 4; ++j) {
            ulonglong2 v; v.x = acc[0][j]; v.y = acc[1][j];
            *(ulonglong2*)&part[ks * 512 + (tb * 4 + j) * 64 + tg * 4] = v;
        }
        __syncthreads();

        // PhaseB: reduce 8 K-partials + xg, gates, state update
        if (tid < 128) {
            float gi = xgi, gf = xgf, gg = xgg, go = xgo;
#pragma unroll
            for (int p = 0; p < 8; ++p) {
                const float* pp = part + p * 512 + pb_b * 64;
                gi += pp[pb_j];
                gf += pp[16 + pb_j];
                gg += pp[32 + pb_j];
                go += pp[48 + pb_j];
            }
            c_reg = sigf(gf) * c_reg + sigf(gi) * tanhf(gg);
            const float hv = sigf(go) * tanhf(c_reg);
            __stcg(&d_hdup[t & 1][g][cbase + pb_j][pb_b], pk2(hv, hv));
            const int srel = dircol ? xs : (t - 496);
            if (srel >= 0)
                d_hsel[((size_t)bglob * 16 + srel) * En + dircol * Hn + cbase + pb_j] = hv;
        }
        gridbar(g);
    }
}

// ======================= K3: weight packing + folds ========================
__global__ void __launch_bounds__(256) k_pack(
    const float* __restrict__ Wk, const float* __restrict__ bk,
    const float* __restrict__ Wv, const float* __restrict__ bv,
    const float* __restrict__ Wq, const float* __restrict__ bq)
{
    const int r = blockIdx.x;
    const float* src = nullptr;
    float bsv = 0.0f;
    if (r < 1024)      { src = Wk + (size_t)r * En;                bsv = bk[r]; }
    else if (r < 2048) { src = Wv + (size_t)(r - 1024) * En;       bsv = bv[r - 1024]; }
    else if (r < 2112) { src = Wq + (size_t)(960 + r - 2048) * En; bsv = bq[960 + r - 2048]; }
    float* dst = d_wpack + (size_t)r * En;
    if (src) {
        for (int i = threadIdx.x * 4; i < En; i += 1024)
            *(float4*)(dst + i) = *(const float4*)(src + i);
    } else {
        const float4 z4 = make_float4(0.f, 0.f, 0.f, 0.f);
        for (int i = threadIdx.x * 4; i < En; i += 1024) *(float4*)(dst + i) = z4;
    }
    if (threadIdx.x == 0) d_bpack[r] = bsv;
}

__global__ void __launch_bounds__(256) k_weff(
    const float* __restrict__ Wfc, const float* __restrict__ Wo,
    const float* __restrict__ bo,  const float* __restrict__ bfc)
{
    const int i = blockIdx.x * 256 + threadIdx.x;   // 0..1023
    float acc = 0.0f;
    for (int e = 0; e < En; ++e) acc += Wfc[e] * Wo[(size_t)e * En + i];
    d_weff[i] = acc;
    if (blockIdx.x == 0) {
        __shared__ float red[256];
        float p = 0.0f;
        for (int e = threadIdx.x; e < En; e += 256) p += Wfc[e] * bo[e];
        red[threadIdx.x] = p; __syncthreads();
        for (int o = 128; o > 0; o >>= 1) {
            if (threadIdx.x < o) red[threadIdx.x] += red[threadIdx.x + o];
            __syncthreads();
        }
        if (threadIdx.x == 0) d_scal0 = red[0] + bfc[0];
    }
}

// ======================= K4: QKV GEMM ======================================
// d_att[m][n] = d_hsel[m] . d_wpack[n] + d_bpack[n]; M=512, N=2176, K=1024.
__global__ void __launch_bounds__(256) k_qkv()
{
    __shared__ __align__(16) float A_sm[8][128];
    __shared__ __align__(16) float B_sm[8][128];
    const int tid = threadIdx.x;
    const int m0 = blockIdx.y * 128;
    const int n0 = blockIdx.x * 128;
    const int lrow = tid >> 1;
    const int lk   = (tid & 1) * 4;
    const float* __restrict__ arow = d_hsel + (size_t)(m0 + lrow) * En;
    const float* __restrict__ wrow = d_wpack + (size_t)(n0 + lrow) * En;
    const int tm = tid >> 4;
    const int tn = tid & 15;

    float acc[8][8];
#pragma unroll
    for (int i = 0; i < 8; ++i)
#pragma unroll
        for (int j = 0; j < 8; ++j) acc[i][j] = 0.0f;

    for (int k0 = 0; k0 < En; k0 += 8) {
        float4 av = *(const float4*)(arow + k0 + lk);
        float4 bv = *(const float4*)(wrow + k0 + lk);
        __syncthreads();
        A_sm[lk + 0][lrow] = av.x; A_sm[lk + 1][lrow] = av.y;
        A_sm[lk + 2][lrow] = av.z; A_sm[lk + 3][lrow] = av.w;
        B_sm[lk + 0][lrow] = bv.x; B_sm[lk + 1][lrow] = bv.y;
        B_sm[lk + 2][lrow] = bv.z; B_sm[lk + 3][lrow] = bv.w;
        __syncthreads();
#pragma unroll
        for (int kk = 0; kk < 8; ++kk) {
            float a[8], b[8];
            *(float4*)(a + 0) = *(const float4*)&A_sm[kk][tm * 8 + 0];
            *(float4*)(a + 4) = *(const float4*)&A_sm[kk][tm * 8 + 4];
            *(float4*)(b + 0) = *(const float4*)&B_sm[kk][tn * 8 + 0];
            *(float4*)(b + 4) = *(const float4*)&B_sm[kk][tn * 8 + 4];
#pragma unroll
            for (int i = 0; i < 8; ++i)
#pragma unroll
                for (int j = 0; j < 8; ++j) acc[i][j] += a[i] * b[j];
        }
    }

    float bvals[8];
#pragma unroll
    for (int j = 0; j < 8; ++j) bvals[j] = d_bpack[n0 + tn * 8 + j];
#pragma unroll
    for (int i = 0; i < 8; ++i) {
        const int m = m0 + tm * 8 + i;
        float* orow = d_att + (size_t)m * NPACK + n0 + tn * 8;
        float4 o0 = make_float4(acc[i][0] + bvals[0], acc[i][1] + bvals[1],
                                acc[i][2] + bvals[2], acc[i][3] + bvals[3]);
        float4 o1 = make_float4(acc[i][4] + bvals[4], acc[i][5] + bvals[5],
                                acc[i][6] + bvals[6], acc[i][7] + bvals[7]);
        *(float4*)(orow + 0) = o0;
        *(float4*)(orow + 4) = o1;
    }
}

// ======================= K5: head-gram softmax + fold ======================
__global__ void __launch_bounds__(512) k_attn(float* __restrict__ out)
{
    __shared__ float sm[16];
    const int b = blockIdx.x;
    const int w = threadIdx.x >> 5;     // srel
    const int lane = threadIdx.x & 31;
    const float* __restrict__ row = d_att + (size_t)(b * 16 + w) * NPACK;

    float sc = 0.0f;
    if (lane < 16) {
        const float4* q4 = (const float4*)(row + 2048);
        const float4* k4 = (const float4*)(row + lane * 64);
#pragma unroll
        for (int i = 0; i < 16; ++i) {
            float4 q = q4[i], k = k4[i];
            sc += q.x * k.x + q.y * k.y + q.z * k.z + q.w * k.w;
        }
        sc *= 0.125f;
    } else sc = -INFINITY;

    float m = sc;
#pragma unroll
    for (int o = 8; o > 0; o >>= 1) m = fmaxf(m, __shfl_xor_sync(0xffffffffu, m, o));
    float e = (lane < 16) ? expf(sc - m) : 0.0f;
    float den = e;
#pragma unroll
    for (int o = 8; o > 0; o >>= 1) den += __shfl_xor_sync(0xffffffffu, den, o);

    float pre0 = 0.0f, pre1 = 0.0f;
#pragma unroll
    for (int kh = 0; kh < 16; ++kh) {
        const float a = __shfl_sync(0xffffffffu, e, kh);
        pre0 += a * row[1024 + kh * 64 + lane];
        pre1 += a * row[1024 + kh * 64 + lane + 32];
    }
    const float dn = __shfl_sync(0xffffffffu, den, 0);
    float acc = (pre0 * d_weff[w * 64 + lane] + pre1 * d_weff[w * 64 + lane + 32]) / dn;
#pragma unroll
    for (int o = 16; o > 0; o >>= 1) acc += __shfl_xor_sync(0xffffffffu, acc, o);
    if (lane == 0) sm[w] = acc;
    __syncthreads();
    if (threadIdx.x == 0) {
        float z = d_scal0;
#pragma unroll
        for (int h = 0; h < 16; ++h) z += sm[h];
        out[b] = 1.0f / (1.0f + expf(-z));
    }
}

// ======================= launch ===========================================
extern "C" void kernel_launch(void* const* d_in, const int* in_sizes, int n_in,
                              void* d_out, int out_size)
{
    const float* x    = (const float*)d_in[0];
    const float* Wihf = (const float*)d_in[1];
    const float* Whhf = (const float*)d_in[2];
    const float* bf   = (const float*)d_in[3];
    const float* Wihb = (const float*)d_in[4];
    const float* Whhb = (const float*)d_in[5];
    const float* bb   = (const float*)d_in[6];
    const float* Wq   = (const float*)d_in[7];
    const float* bq   = (const float*)d_in[8];
    const float* Wk   = (const float*)d_in[9];
    const float* bk   = (const float*)d_in[10];
    const float* Wv   = (const float*)d_in[11];
    const float* bv   = (const float*)d_in[12];
    const float* Wo   = (const float*)d_in[13];
    const float* bo   = (const float*)d_in[14];
    const float* Wfc  = (const float*)d_in[15];
    const float* bfc  = (const float*)d_in[16];
    float* out = (float*)d_out;

    // smem: W 128KB + hdup 32KB + part 16KB = 176KB
    const int rec_smem = 512 * 64 * 4 + 512 * 8 * 8 + 8 * 8 * 64 * 4;
    cudaFuncSetAttribute(k_rec, cudaFuncAttributeMaxDynamicSharedMemorySize, rec_smem);

    k_xg<<<dim3(16, 132), 256>>>(x, Wihf, bf, Wihb, bb);
    k_rec<<<128, 256, rec_smem>>>(Whhf, 512, 0);
    k_rec<<<128, 256, rec_smem>>>(Whhb, 16, 1);
    k_pack<<<NPACK, 256>>>(Wk, bk, Wv, bv, Wq, bq);
    k_weff<<<4, 256>>>(Wfc, Wo, bo, bfc);
    k_qkv<<<dim3(17, 4), 256>>>();
    k_attn<<<32, 512>>>(out);
}

// round 8
// speedup vs baseline: 1.5476x; 1.2720x over previous
#include <cuda_runtime.h>
#include <math.h>
#include <stdint.h>

// dims
#define Bn   32
#define Sn   512
#define In   256
#define Hn   512
#define G4n  2048
#define En   1024
#define NPACK 2176   // 1024 K-rows + 1024 V-rows + 64 Q15-rows + 64 zero pad
#define NGRP 4       // batch groups (8 batches each), 32 blocks per group

// ---------------- static device scratch ----------------
__device__ float d_xg [(size_t)Sn * Bn * G4n];   // fwd input gates, row m=s*32+b, col g (128 MB)
__device__ float d_xgb[(size_t)16 * Bn * G4n];   // bwd input gates, row m=srel*32+b
__device__ unsigned long long d_hdup[2][NGRP][Hn][8]; // h state, duplicated f32x2, dbl-buffered
__device__ float d_hsel[(size_t)Bn * 16 * En];   // h at s in [496,512): [(b*16+srel)][e]
__device__ float d_wpack[(size_t)NPACK * En];
__device__ float d_bpack[NPACK];
__device__ float d_att[(size_t)512 * NPACK];     // per (b,srel): K(1024) V(1024) Q15(64)
__device__ float d_weff[En];
__device__ float d_scal0;

// barrier state: each word in its OWN 128-byte L2 line (no false sharing
// between cnt/gen or across groups)
struct __align__(128) BarLine { unsigned v; unsigned pad[31]; };
__device__ BarLine d_bcnt[NGRP];
__device__ BarLine d_bgen[NGRP];

__device__ __forceinline__ float sigf(float x) { return 1.0f / (1.0f + expf(-x)); }

__device__ __forceinline__ unsigned ld_acq(const unsigned* p) {
    unsigned v;
    asm volatile("ld.acquire.gpu.u32 %0, [%1];" : "=r"(v) : "l"(p) : "memory");
    return v;
}
__device__ __forceinline__ void st_rel(unsigned* p, unsigned v) {
    asm volatile("st.release.gpu.u32 [%0], %1;" :: "l"(p), "r"(v) : "memory");
}

// ---- packed fp32x2 helpers (bit-exact 2x fp32 FMA; sm_100+ PTX) ----
__device__ __forceinline__ unsigned long long ffma2(
    unsigned long long a, unsigned long long b, unsigned long long c) {
    unsigned long long d;
    asm("fma.rn.f32x2 %0, %1, %2, %3;" : "=l"(d) : "l"(a), "l"(b), "l"(c));
    return d;
}
__device__ __forceinline__ unsigned long long pk2(float x, float y) {
    unsigned long long r;
    asm("mov.b64 %0, {%1, %2};" : "=l"(r)
        : "r"(__float_as_uint(x)), "r"(__float_as_uint(y)));
    return r;
}
__device__ __forceinline__ void upk2(unsigned long long v, float& x, float& y) {
    unsigned lo, hi;
    asm("mov.b64 {%0, %1}, %2;" : "=r"(lo), "=r"(hi) : "l"(v));
    x = __uint_as_float(lo); y = __uint_as_float(hi);
}

// ======================= K1: xg = x @ W_ih^T + b ===========================
// M = 16384 fwd rows (m=s*32+b) + 512 bwd rows (s in [496,512)).
// 128x128 tile, 256 thr, 8x8 microtile via f32x2, BK=8. Row-major output.
__global__ void __launch_bounds__(256) k_xg(
    const float* __restrict__ x,
    const float* __restrict__ Wihf, const float* __restrict__ bf,
    const float* __restrict__ Wihb, const float* __restrict__ bb)
{
    __shared__ __align__(16) float A_sm[8][128];
    __shared__ __align__(16) float B_sm[8][128];
    const int tid = threadIdx.x;
    const bool bwd = (blockIdx.y >= 128);
    const float* __restrict__ W    = bwd ? Wihb : Wihf;
    const float* __restrict__ bias = bwd ? bb   : bf;
    const int m0 = blockIdx.y * 128;
    const int n0 = blockIdx.x * 128;

    const int lrow = tid >> 1;
    const int lk   = (tid & 1) * 4;
    const int mg = m0 + lrow;
    int sA, bA;
    if (!bwd) { sA = mg >> 5; bA = mg & 31; }
    else { const int ml = mg - 16384; sA = 496 + (ml >> 5); bA = ml & 31; }
    const float* __restrict__ xrow = x + ((size_t)bA * Sn + sA) * In;
    const float* __restrict__ wrow = W + (size_t)(n0 + lrow) * In;

    const int tm = tid >> 4;
    const int tn = tid & 15;

    unsigned long long acc[8][4];
#pragma unroll
    for (int i = 0; i < 8; ++i)
#pragma unroll
        for (int p = 0; p < 4; ++p) acc[i][p] = 0ull;

    for (int k0 = 0; k0 < In; k0 += 8) {
        float4 av = *(const float4*)(xrow + k0 + lk);
        float4 bv = *(const float4*)(wrow + k0 + lk);
        __syncthreads();
        A_sm[lk + 0][lrow] = av.x; A_sm[lk + 1][lrow] = av.y;
        A_sm[lk + 2][lrow] = av.z; A_sm[lk + 3][lrow] = av.w;
        B_sm[lk + 0][lrow] = bv.x; B_sm[lk + 1][lrow] = bv.y;
        B_sm[lk + 2][lrow] = bv.z; B_sm[lk + 3][lrow] = bv.w;
        __syncthreads();
#pragma unroll
        for (int kk = 0; kk < 8; ++kk) {
            float a[8];
            *(float4*)(a + 0) = *(const float4*)&A_sm[kk][tm * 8 + 0];
            *(float4*)(a + 4) = *(const float4*)&A_sm[kk][tm * 8 + 4];
            ulonglong2 b01 = *(const ulonglong2*)&B_sm[kk][tn * 8 + 0];
            ulonglong2 b23 = *(const ulonglong2*)&B_sm[kk][tn * 8 + 4];
            unsigned long long bb4[4] = {b01.x, b01.y, b23.x, b23.y};
#pragma unroll
            for (int i = 0; i < 8; ++i) {
                const unsigned long long ad = pk2(a[i], a[i]);
#pragma unroll
                for (int p = 0; p < 4; ++p) acc[i][p] = ffma2(ad, bb4[p], acc[i][p]);
            }
        }
    }

    float bvals[8];
#pragma unroll
    for (int j = 0; j < 8; ++j) bvals[j] = bias[n0 + tn * 8 + j];
#pragma unroll
    for (int i = 0; i < 8; ++i) {
        float c[8];
#pragma unroll
        for (int p = 0; p < 4; ++p) upk2(acc[i][p], c[2 * p], c[2 * p + 1]);
        const int m = m0 + tm * 8 + i;
        float* orow = (!bwd ? d_xg + (size_t)m * G4n
                            : d_xgb + (size_t)(m - 16384) * G4n) + n0 + tn * 8;
        float4 o0 = make_float4(c[0] + bvals[0], c[1] + bvals[1],
                                c[2] + bvals[2], c[3] + bvals[3]);
        float4 o1 = make_float4(c[4] + bvals[4], c[5] + bvals[5],
                                c[6] + bvals[6], c[7] + bvals[7]);
        *(float4*)(orow + 0) = o0;
        *(float4*)(orow + 4) = o1;
    }
}

// ======================= K2: persistent LSTM recurrence ====================
// 128 blocks = 4 independent batch-groups x 32 blocks.
// Split-phase padded barrier; next-step xg prefetch inside the arrive->wait
// window (covers its DRAM latency with barrier skew).
__global__ void __launch_bounds__(256) k_rec(
    const float* __restrict__ Whh, int steps, int dircol)
{
    extern __shared__ float smem[];
    float* W_sm = smem;                                        // [512][64]
    unsigned long long* hdup = (unsigned long long*)(smem + 512 * 64); // [512][8]
    float* part = (float*)(hdup + 512 * 8);                    // [8][8][64]

    const int tid  = threadIdx.x;
    const int g    = blockIdx.x & 3;
    const int rblk = blockIdx.x >> 2;
    const int cbase = rblk * 16;

    // preload W transposed: W_sm[k][r], r = q*16+j  <- Whh row q*512+cbase+j
    {
        const int r = tid & 63;
        const int q = r >> 4, j = r & 15;
        const int kblk = tid >> 6;            // 4 chunks of 128 k
        const float* wr = Whh + (size_t)(q * Hn + cbase + j) * Hn + kblk * 128;
#pragma unroll 4
        for (int kk = 0; kk < 128; kk += 4) {
            float4 w4 = *(const float4*)(wr + kk);
            const int kb = kblk * 128 + kk;
            W_sm[(kb + 0) * 64 + r] = w4.x;
            W_sm[(kb + 1) * 64 + r] = w4.y;
            W_sm[(kb + 2) * 64 + r] = w4.z;
            W_sm[(kb + 3) * 64 + r] = w4.w;
        }
    }

    const int ks = tid >> 5;            // K-split 8 (warp-uniform)
    const int tg = (tid >> 1) & 15;     // row-quad
    const int tb = tid & 1;             // batch-quad (2 x 4 batches)

    // PhaseB identity (threads 0..127): cell pb_j of batch pb_b
    const int pb_b = tid >> 4;
    const int pb_j = tid & 15;
    const int bglob = g * 8 + pb_b;

    float c_reg = 0.0f;

    // initial xg prefetch (for t = 0)
    float xgi = 0.f, xgf = 0.f, xgg = 0.f, xgo = 0.f;
    if (tid < 128) {
        const int xs0 = dircol ? (steps - 1) : 0;
        const float* xb = (dircol ? d_xgb : d_xg)
                        + (size_t)(xs0 * 32 + bglob) * G4n + cbase + pb_j;
        xgi = __ldg(xb);
        xgf = __ldg(xb + 512);
        xgg = __ldg(xb + 1024);
        xgo = __ldg(xb + 1536);
    }

    unsigned btarget = 0;

    for (int t = 0; t < steps; ++t) {
        const int xs = dircol ? (steps - 1 - t) : t;

        // stage h(t-1) duplicated pairs into smem (32 KB)
        if (t == 0) {
            for (int i = tid; i < 4096; i += 256) hdup[i] = 0ull;
        } else {
            const uint4* src = (const uint4*)&d_hdup[(t - 1) & 1][g][0][0];
            uint4* dst = (uint4*)hdup;
#pragma unroll
            for (int i = 0; i < 8; ++i)
                dst[tid + 256 * i] = __ldcg(src + tid + 256 * i);
        }
        __syncthreads();

        // GEMM: 64 rows x 8 batches, K-slice [ks*64, ks*64+64)
        unsigned long long acc[2][4];
#pragma unroll
        for (int p = 0; p < 2; ++p)
#pragma unroll
            for (int j = 0; j < 4; ++j) acc[p][j] = 0ull;

        const float* wp = W_sm + (ks * 64) * 64 + tg * 4;
        const unsigned long long* hp = hdup + (ks * 64) * 8 + tb * 4;
#pragma unroll 4
        for (int k = 0; k < 64; ++k) {
            ulonglong2 w2  = *(const ulonglong2*)wp;       wp += 64;
            ulonglong2 h01 = *(const ulonglong2*)hp;
            ulonglong2 h23 = *(const ulonglong2*)(hp + 2); hp += 8;
            acc[0][0] = ffma2(w2.x, h01.x, acc[0][0]);
            acc[1][0] = ffma2(w2.y, h01.x, acc[1][0]);
            acc[0][1] = ffma2(w2.x, h01.y, acc[0][1]);
            acc[1][1] = ffma2(w2.y, h01.y, acc[1][1]);
            acc[0][2] = ffma2(w2.x, h23.x, acc[0][2]);
            acc[1][2] = ffma2(w2.y, h23.x, acc[1][2]);
            acc[0][3] = ffma2(w2.x, h23.y, acc[0][3]);
            acc[1][3] = ffma2(w2.y, h23.y, acc[1][3]);
        }
#pragma unroll
        for (int j = 0; j < 4; ++j) {
            ulonglong2 v; v.x = acc[0][j]; v.y = acc[1][j];
            *(ulonglong2*)&part[ks * 512 + (tb * 4 + j) * 64 + tg * 4] = v;
        }
        __syncthreads();

        // PhaseB: reduce 8 K-partials + xg, gates, state update
        if (tid < 128) {
            float gi = xgi, gf = xgf, gg = xgg, go = xgo;
#pragma unroll
            for (int p = 0; p < 8; ++p) {
                const float* pp = part + p * 512 + pb_b * 64;
                gi += pp[pb_j];
                gf += pp[16 + pb_j];
                gg += pp[32 + pb_j];
                go += pp[48 + pb_j];
            }
            c_reg = sigf(gf) * c_reg + sigf(gi) * tanhf(gg);
            const float hv = sigf(go) * tanhf(c_reg);
            __stcg(&d_hdup[t & 1][g][cbase + pb_j][pb_b], pk2(hv, hv));
            const int srel = dircol ? xs : (t - 496);
            if (srel >= 0)
                d_hsel[((size_t)bglob * 16 + srel) * En + dircol * Hn + cbase + pb_j] = hv;
        }

        // ---- barrier arrive (split phase) ----
        __syncthreads();   // all PhaseB stores issued
        if (tid == 0) {
            __threadfence();
            const unsigned cur = *(volatile unsigned*)&d_bgen[g].v;
            btarget = cur + 1u;
            if (atomicAdd(&d_bcnt[g].v, 1u) == 31u) {
                d_bcnt[g].v = 0u;
                st_rel(&d_bgen[g].v, btarget);
            }
        }

        // ---- prefetch next step's xg (DRAM latency hidden in barrier wait) ----
        if (tid < 128 && t + 1 < steps) {
            const int xs1 = dircol ? (steps - 2 - t) : (t + 1);
            const float* xb = (dircol ? d_xgb : d_xg)
                            + (size_t)(xs1 * 32 + bglob) * G4n + cbase + pb_j;
            xgi = __ldg(xb);
            xgf = __ldg(xb + 512);
            xgg = __ldg(xb + 1024);
            xgo = __ldg(xb + 1536);
        }

        // ---- barrier wait ----
        if (tid == 0) {
            while (ld_acq(&d_bgen[g].v) < btarget) { }
        }
        __syncthreads();
    }
}

// ======================= K3: weight packing + folds ========================
__global__ void __launch_bounds__(256) k_pack(
    const float* __restrict__ Wk, const float* __restrict__ bk,
    const float* __restrict__ Wv, const float* __restrict__ bv,
    const float* __restrict__ Wq, const float* __restrict__ bq)
{
    const int r = blockIdx.x;
    const float* src = nullptr;
    float bsv = 0.0f;
    if (r < 1024)      { src = Wk + (size_t)r * En;                bsv = bk[r]; }
    else if (r < 2048) { src = Wv + (size_t)(r - 1024) * En;       bsv = bv[r - 1024]; }
    else if (r < 2112) { src = Wq + (size_t)(960 + r - 2048) * En; bsv = bq[960 + r - 2048]; }
    float* dst = d_wpack + (size_t)r * En;
    if (src) {
        for (int i = threadIdx.x * 4; i < En; i += 1024)
            *(float4*)(dst + i) = *(const float4*)(src + i);
    } else {
        const float4 z4 = make_float4(0.f, 0.f, 0.f, 0.f);
        for (int i = threadIdx.x * 4; i < En; i += 1024) *(float4*)(dst + i) = z4;
    }
    if (threadIdx.x == 0) d_bpack[r] = bsv;
}

__global__ void __launch_bounds__(256) k_weff(
    const float* __restrict__ Wfc, const float* __restrict__ Wo,
    const float* __restrict__ bo,  const float* __restrict__ bfc)
{
    const int i = blockIdx.x * 256 + threadIdx.x;   // 0..1023
    float acc = 0.0f;
    for (int e = 0; e < En; ++e) acc += Wfc[e] * Wo[(size_t)e * En + i];
    d_weff[i] = acc;
    if (blockIdx.x == 0) {
        __shared__ float red[256];
        float p = 0.0f;
        for (int e = threadIdx.x; e < En; e += 256) p += Wfc[e] * bo[e];
        red[threadIdx.x] = p; __syncthreads();
        for (int o = 128; o > 0; o >>= 1) {
            if (threadIdx.x < o) red[threadIdx.x] += red[threadIdx.x + o];
            __syncthreads();
        }
        if (threadIdx.x == 0) d_scal0 = red[0] + bfc[0];
    }
}

// ======================= K4: QKV GEMM ======================================
// d_att[m][n] = d_hsel[m] . d_wpack[n] + d_bpack[n]; M=512, N=2176, K=1024.
__global__ void __launch_bounds__(256) k_qkv()
{
    __shared__ __align__(16) float A_sm[8][128];
    __shared__ __align__(16) float B_sm[8][128];
    const int tid = threadIdx.x;
    const int m0 = blockIdx.y * 128;
    const int n0 = blockIdx.x * 128;
    const int lrow = tid >> 1;
    const int lk   = (tid & 1) * 4;
    const float* __restrict__ arow = d_hsel + (size_t)(m0 + lrow) * En;
    const float* __restrict__ wrow = d_wpack + (size_t)(n0 + lrow) * En;
    const int tm = tid >> 4;
    const int tn = tid & 15;

    unsigned long long acc[8][4];
#pragma unroll
    for (int i = 0; i < 8; ++i)
#pragma unroll
        for (int p = 0; p < 4; ++p) acc[i][p] = 0ull;

    for (int k0 = 0; k0 < En; k0 += 8) {
        float4 av = *(const float4*)(arow + k0 + lk);
        float4 bv = *(const float4*)(wrow + k0 + lk);
        __syncthreads();
        A_sm[lk + 0][lrow] = av.x; A_sm[lk + 1][lrow] = av.y;
        A_sm[lk + 2][lrow] = av.z; A_sm[lk + 3][lrow] = av.w;
        B_sm[lk + 0][lrow] = bv.x; B_sm[lk + 1][lrow] = bv.y;
        B_sm[lk + 2][lrow] = bv.z; B_sm[lk + 3][lrow] = bv.w;
        __syncthreads();
#pragma unroll
        for (int kk = 0; kk < 8; ++kk) {
            float a[8];
            *(float4*)(a + 0) = *(const float4*)&A_sm[kk][tm * 8 + 0];
            *(float4*)(a + 4) = *(const float4*)&A_sm[kk][tm * 8 + 4];
            ulonglong2 b01 = *(const ulonglong2*)&B_sm[kk][tn * 8 + 0];
            ulonglong2 b23 = *(const ulonglong2*)&B_sm[kk][tn * 8 + 4];
            unsigned long long bb4[4] = {b01.x, b01.y, b23.x, b23.y};
#pragma unroll
            for (int i = 0; i < 8; ++i) {
                const unsigned long long ad = pk2(a[i], a[i]);
#pragma unroll
                for (int p = 0; p < 4; ++p) acc[i][p] = ffma2(ad, bb4[p], acc[i][p]);
            }
        }
    }

    float bvals[8];
#pragma unroll
    for (int j = 0; j < 8; ++j) bvals[j] = d_bpack[n0 + tn * 8 + j];
#pragma unroll
    for (int i = 0; i < 8; ++i) {
        float c[8];
#pragma unroll
        for (int p = 0; p < 4; ++p) upk2(acc[i][p], c[2 * p], c[2 * p + 1]);
        const int m = m0 + tm * 8 + i;
        float* orow = d_att + (size_t)m * NPACK + n0 + tn * 8;
        float4 o0 = make_float4(c[0] + bvals[0], c[1] + bvals[1],
                                c[2] + bvals[2], c[3] + bvals[3]);
        float4 o1 = make_float4(c[4] + bvals[4], c[5] + bvals[5],
                                c[6] + bvals[6], c[7] + bvals[7]);
        *(float4*)(orow + 0) = o0;
        *(float4*)(orow + 4) = o1;
    }
}

// ======================= K5: head-gram softmax + fold ======================
__global__ void __launch_bounds__(512) k_attn(float* __restrict__ out)
{
    __shared__ float sm[16];
    const int b = blockIdx.x;
    const int w = threadIdx.x >> 5;     // srel
    const int lane = threadIdx.x & 31;
    const float* __restrict__ row = d_att + (size_t)(b * 16 + w) * NPACK;

    float sc = 0.0f;
    if (lane < 16) {
        const float4* q4 = (const float4*)(row + 2048);
        const float4* k4 = (const float4*)(row + lane * 64);
#pragma unroll
        for (int i = 0; i < 16; ++i) {
            float4 q = q4[i], k = k4[i];
            sc += q.x * k.x + q.y * k.y + q.z * k.z + q.w * k.w;
        }
        sc *= 0.125f;
    } else sc = -INFINITY;

    float m = sc;
#pragma unroll
    for (int o = 8; o > 0; o >>= 1) m = fmaxf(m, __shfl_xor_sync(0xffffffffu, m, o));
    float e = (lane < 16) ? expf(sc - m) : 0.0f;
    float den = e;
#pragma unroll
    for (int o = 8; o > 0; o >>= 1) den += __shfl_xor_sync(0xffffffffu, den, o);

    float pre0 = 0.0f, pre1 = 0.0f;
#pragma unroll
    for (int kh = 0; kh < 16; ++kh) {
        const float a = __shfl_sync(0xffffffffu, e, kh);
        pre0 += a * row[1024 + kh * 64 + lane];
        pre1 += a * row[1024 + kh * 64 + lane + 32];
    }
    const float dn = __shfl_sync(0xffffffffu, den, 0);
    float acc = (pre0 * d_weff[w * 64 + lane] + pre1 * d_weff[w * 64 + lane + 32]) / dn;
#pragma unroll
    for (int o = 16; o > 0; o >>= 1) acc += __shfl_xor_sync(0xffffffffu, acc, o);
    if (lane == 0) sm[w] = acc;
    __syncthreads();
    if (threadIdx.x == 0) {
        float z = d_scal0;
#pragma unroll
        for (int h = 0; h < 16; ++h) z += sm[h];
        out[b] = 1.0f / (1.0f + expf(-z));
    }
}

// ======================= launch ===========================================
extern "C" void kernel_launch(void* const* d_in, const int* in_sizes, int n_in,
                              void* d_out, int out_size)
{
    const float* x    = (const float*)d_in[0];
    const float* Wihf = (const float*)d_in[1];
    const float* Whhf = (const float*)d_in[2];
    const float* bf   = (const float*)d_in[3];
    const float* Wihb = (const float*)d_in[4];
    const float* Whhb = (const float*)d_in[5];
    const float* bb   = (const float*)d_in[6];
    const float* Wq   = (const float*)d_in[7];
    const float* bq   = (const float*)d_in[8];
    const float* Wk   = (const float*)d_in[9];
    const float* bk   = (const float*)d_in[10];
    const float* Wv   = (const float*)d_in[11];
    const float* bv   = (const float*)d_in[12];
    const float* Wo   = (const float*)d_in[13];
    const float* bo   = (const float*)d_in[14];
    const float* Wfc  = (const float*)d_in[15];
    const float* bfc  = (const float*)d_in[16];
    float* out = (float*)d_out;

    // smem: W 128KB + hdup 32KB + part 16KB = 176KB
    const int rec_smem = 512 * 64 * 4 + 512 * 8 * 8 + 8 * 8 * 64 * 4;
    cudaFuncSetAttribute(k_rec, cudaFuncAttributeMaxDynamicSharedMemorySize, rec_smem);

    k_xg<<<dim3(16, 132), 256>>>(x, Wihf, bf, Wihb, bb);
    k_rec<<<128, 256, rec_smem>>>(Whhf, 512, 0);
    k_rec<<<128, 256, rec_smem>>>(Whhb, 16, 1);
    k_pack<<<NPACK, 256>>>(Wk, bk, Wv, bv, Wq, bq);
    k_weff<<<4, 256>>>(Wfc, Wo, bo, bfc);
    k_qkv<<<dim3(17, 4), 256>>>();
    k_attn<<<32, 512>>>(out);
}